// round 6
// baseline (speedup 1.0000x reference)
#include <cuda_runtime.h>
#include <cstdint>

#define NGRAPH 2048
#define NPG 91
#define DIM 128
#define ORDER 3

// scratch: fv[o,b,:] = feats[last_idx[o,b]] @ Wv[o] + bu[o]  (3 MB)
__device__ float g_fvb[ORDER * NGRAPH * DIM];

// ---------------- kernel 1: fvb ----------------
__global__ void __launch_bounds__(128) fvb_kernel(const float* __restrict__ feats,
                                                  const float* __restrict__ Wv,
                                                  const float* __restrict__ bu,
                                                  const int* __restrict__ last_idx) {
    const int GPB = 16;
    int o  = blockIdx.x / (NGRAPH / GPB);
    int b0 = (blockIdx.x % (NGRAPH / GPB)) * GPB;
    int h  = threadIdx.x;
    __shared__ float xs[GPB][DIM];
    #pragma unroll
    for (int j = 0; j < GPB; j++) {
        int node = last_idx[o * NGRAPH + b0 + j];
        xs[j][h] = feats[node * DIM + h];
    }
    __syncthreads();
    float acc[GPB];
    float bv = bu[o * DIM + h];
    #pragma unroll
    for (int j = 0; j < GPB; j++) acc[j] = bv;
    const float* Wvo = Wv + o * DIM * DIM;
    #pragma unroll 4
    for (int d = 0; d < DIM; d++) {
        float w = Wvo[d * DIM + h];
        #pragma unroll
        for (int j = 0; j < GPB; j++) acc[j] += xs[j][d] * w;
    }
    #pragma unroll
    for (int j = 0; j < GPB; j++)
        g_fvb[(o * NGRAPH + b0 + j) * DIM + h] = acc[j];
}

// ---------------- fused main kernel ----------------
#define MROWS 192
#define LDA 132   // A smem stride (conflict-free frag loads: 132%32==4)
#define LDB 136   // B smem stride (conflict-free:          136%32==8)
#define OFF_A  0
#define OFF_WU (OFF_A + MROWS * LDA)        // 25344
#define OFF_FV (OFF_WU + 128 * LDB)         // 25344+17408 = 42752
#define OFF_WE (OFF_FV + 256)               // 43008
#define OFF_ER (OFF_WE + 128)               // 43136
#define OFF_AL (OFF_ER + 384)               // 43520
#define SMEM_FLOATS (OFF_AL + 192)          // 43712 -> 174848 B

__device__ __forceinline__ uint32_t to_tf32(float x) {
    uint32_t u;
    asm("cvt.rna.tf32.f32 %0, %1;" : "=r"(u) : "f"(x));
    return u;
}
__device__ __forceinline__ void mma_tf32(float c[4], const uint32_t a[4], const uint32_t b[2]) {
    asm volatile(
        "mma.sync.aligned.m16n8k8.row.col.f32.tf32.tf32.f32 "
        "{%0,%1,%2,%3}, {%4,%5,%6,%7}, {%8,%9}, {%0,%1,%2,%3};"
        : "+f"(c[0]), "+f"(c[1]), "+f"(c[2]), "+f"(c[3])
        : "r"(a[0]), "r"(a[1]), "r"(a[2]), "r"(a[3]), "r"(b[0]), "r"(b[1]));
}

__global__ void __launch_bounds__(256, 1) fused_kernel(const float* __restrict__ feats,
                                                       const float* __restrict__ Wu,
                                                       const float* __restrict__ We,
                                                       float* __restrict__ out) {
    extern __shared__ float sm[];
    float* sA  = sm + OFF_A;
    float* sWu = sm + OFF_WU;
    float* sFV = sm + OFF_FV;
    float* sWe = sm + OFF_WE;
    float* sER = sm + OFF_ER;
    float* sAL = sm + OFF_AL;

    const int tid   = threadIdx.x;
    const int g0    = blockIdx.x * 2;       // 2 graphs per CTA
    const int lane  = tid & 31;
    const int wid   = tid >> 5;
    const int warpM = wid >> 1;             // 0..3
    const int warpN = wid & 1;              // 0..1
    const int gid   = lane >> 2;
    const int tig   = lane & 3;

    // stage feats: 182 contiguous node rows (+10 zero pad rows)
    {
        const float4* f4 = (const float4*)(feats + g0 * NPG * DIM);
        for (int i = tid; i < 182 * 32; i += 256) {
            int r = i >> 5, c = i & 31;
            *(float4*)(sA + r * LDA + c * 4) = f4[i];
        }
        for (int i = tid; i < 10 * 32; i += 256) {
            int r = 182 + (i >> 5), c = i & 31;
            *(float4*)(sA + r * LDA + c * 4) = make_float4(0.f, 0.f, 0.f, 0.f);
        }
    }

    for (int o = 0; o < ORDER; o++) {
        if (o > 0) __syncthreads();
        // stage Wu[o] (pre-rounded to tf32), fv+bu for both graphs, We[o]
        {
            const float4* w4 = (const float4*)(Wu + o * DIM * DIM);
            for (int i = tid; i < 128 * 32; i += 256) {
                int r = i >> 5, c = i & 31;
                float4 v = w4[i];
                uint32_t* d = (uint32_t*)(sWu + r * LDB + c * 4);
                d[0] = to_tf32(v.x); d[1] = to_tf32(v.y);
                d[2] = to_tf32(v.z); d[3] = to_tf32(v.w);
            }
            int g = tid >> 7, h = tid & 127;
            sFV[tid] = g_fvb[(o * NGRAPH + g0 + g) * DIM + h];
            if (tid < 128) sWe[tid] = We[o * DIM + tid];
        }
        __syncthreads();

        float acc[3][8][4];
        #pragma unroll
        for (int mt = 0; mt < 3; mt++)
            #pragma unroll
            for (int nt = 0; nt < 8; nt++) {
                acc[mt][nt][0] = 0.f; acc[mt][nt][1] = 0.f;
                acc[mt][nt][2] = 0.f; acc[mt][nt][3] = 0.f;
            }

        #pragma unroll
        for (int ks = 0; ks < 16; ks++) {
            const int k0 = ks * 8;
            uint32_t afr[3][4];
            #pragma unroll
            for (int mt = 0; mt < 3; mt++) {
                const float* base = sA + (warpM * 48 + mt * 16 + gid) * LDA + k0 + tig;
                afr[mt][0] = to_tf32(base[0]);
                afr[mt][1] = to_tf32(base[8 * LDA]);
                afr[mt][2] = to_tf32(base[4]);
                afr[mt][3] = to_tf32(base[8 * LDA + 4]);
            }
            uint32_t bfr[8][2];
            #pragma unroll
            for (int nt = 0; nt < 8; nt++) {
                const uint32_t* base =
                    (const uint32_t*)(sWu + (k0 + tig) * LDB + warpN * 64 + nt * 8 + gid);
                bfr[nt][0] = base[0];
                bfr[nt][1] = base[4 * LDB];
            }
            #pragma unroll
            for (int mt = 0; mt < 3; mt++)
                #pragma unroll
                for (int nt = 0; nt < 8; nt++)
                    mma_tf32(acc[mt][nt], afr[mt], bfr[nt]);
        }

        // epilogue: e[m] partials = sum_h sigmoid(acc + fv + bu) * We[h]
        float ep[3][2];
        #pragma unroll
        for (int mt = 0; mt < 3; mt++) { ep[mt][0] = 0.f; ep[mt][1] = 0.f; }
        #pragma unroll
        for (int mt = 0; mt < 3; mt++) {
            int m0 = warpM * 48 + mt * 16 + gid;
            int m1 = m0 + 8;
            int fo0 = (m0 < NPG ? 0 : DIM);
            int fo1 = (m1 < NPG ? 0 : DIM);
            #pragma unroll
            for (int nt = 0; nt < 8; nt++) {
                int h = warpN * 64 + nt * 8 + tig * 2;
                float we0 = sWe[h], we1 = sWe[h + 1];
                if (m0 < 182) {
                    float v0 = acc[mt][nt][0] + sFV[fo0 + h];
                    float v1 = acc[mt][nt][1] + sFV[fo0 + h + 1];
                    ep[mt][0] += __fdividef(we0, 1.f + __expf(-v0))
                               + __fdividef(we1, 1.f + __expf(-v1));
                }
                if (m1 < 182) {
                    float v2 = acc[mt][nt][2] + sFV[fo1 + h];
                    float v3 = acc[mt][nt][3] + sFV[fo1 + h + 1];
                    ep[mt][1] += __fdividef(we0, 1.f + __expf(-v2))
                               + __fdividef(we1, 1.f + __expf(-v3));
                }
            }
        }
        #pragma unroll
        for (int mt = 0; mt < 3; mt++)
            #pragma unroll
            for (int q = 0; q < 2; q++) {
                float v = ep[mt][q];
                v += __shfl_xor_sync(0xffffffffu, v, 1);
                v += __shfl_xor_sync(0xffffffffu, v, 2);
                if (tig == 0)
                    sER[warpN * 192 + warpM * 48 + mt * 16 + gid + q * 8] = v;
            }
        __syncthreads();

        // per-graph softmax over 91 nodes (warp 0 -> graph 0, warp 1 -> graph 1)
        if (wid < 2) {
            int gbase = wid * NPG;
            float ev[3];
            #pragma unroll
            for (int j = 0; j < 3; j++) {
                int r = lane + 32 * j;
                ev[j] = (r < NPG) ? (sER[gbase + r] + sER[192 + gbase + r]) : -1e30f;
            }
            float mx = fmaxf(ev[0], fmaxf(ev[1], ev[2]));
            #pragma unroll
            for (int s = 16; s; s >>= 1)
                mx = fmaxf(mx, __shfl_xor_sync(0xffffffffu, mx, s));
            float sum = 0.f;
            #pragma unroll
            for (int j = 0; j < 3; j++) {
                ev[j] = (lane + 32 * j < NPG) ? __expf(ev[j] - mx) : 0.f;
                sum += ev[j];
            }
            #pragma unroll
            for (int s = 16; s; s >>= 1)
                sum += __shfl_xor_sync(0xffffffffu, sum, s);
            float inv = 1.f / sum;
            #pragma unroll
            for (int j = 0; j < 3; j++) {
                int r = lane + 32 * j;
                if (r < NPG) sAL[gbase + r] = ev[j] * inv;
            }
        }
        __syncthreads();

        // rst[b,o,:] = sum_m alpha[m] * feats[m,:]
        {
            int g = tid >> 7, h = tid & 127;
            const float* aBase  = sA + g * NPG * LDA + h;
            const float* alBase = sAL + g * NPG;
            float r0 = 0.f;
            #pragma unroll 7
            for (int r = 0; r < NPG; r++) r0 += alBase[r] * aBase[r * LDA];
            out[((g0 + g) * ORDER + o) * DIM + h] = r0;
        }
    }
}

extern "C" void kernel_launch(void* const* d_in, const int* in_sizes, int n_in,
                              void* d_out, int out_size) {
    const float* feats    = (const float*)d_in[0];
    const float* Wu       = (const float*)d_in[1];
    const float* bu       = (const float*)d_in[2];
    const float* Wv       = (const float*)d_in[3];
    const float* We       = (const float*)d_in[4];
    const int*   last_idx = (const int*)d_in[6];
    float* out = (float*)d_out;

    fvb_kernel<<<ORDER * (NGRAPH / 16), 128>>>(feats, Wv, bu, last_idx);

    cudaFuncSetAttribute(fused_kernel, cudaFuncAttributeMaxDynamicSharedMemorySize,
                         SMEM_FLOATS * (int)sizeof(float));
    fused_kernel<<<NGRAPH / 2, 256, SMEM_FLOATS * sizeof(float)>>>(feats, Wu, We, out);
}

// round 7
// speedup vs baseline: 1.0595x; 1.0595x over previous
#include <cuda_runtime.h>
#include <cstdint>

#define NGRAPH 2048
#define NPG 91
#define DIM 128
#define ORDER 3

// scratch: fv[o,b,:] = feats[last_idx[o,b]] @ Wv[o] + bu[o]  (3 MB)
__device__ float g_fvb[ORDER * NGRAPH * DIM];

// ---------------- kernel 1: fvb ----------------
__global__ void __launch_bounds__(128) fvb_kernel(const float* __restrict__ feats,
                                                  const float* __restrict__ Wv,
                                                  const float* __restrict__ bu,
                                                  const int* __restrict__ last_idx) {
    const int GPB = 16;
    int o  = blockIdx.x / (NGRAPH / GPB);
    int b0 = (blockIdx.x % (NGRAPH / GPB)) * GPB;
    int h  = threadIdx.x;
    __shared__ float xs[GPB][DIM];
    #pragma unroll
    for (int j = 0; j < GPB; j++) {
        int node = last_idx[o * NGRAPH + b0 + j];
        xs[j][h] = feats[node * DIM + h];
    }
    __syncthreads();
    float acc[GPB];
    float bv = bu[o * DIM + h];
    #pragma unroll
    for (int j = 0; j < GPB; j++) acc[j] = bv;
    const float* Wvo = Wv + o * DIM * DIM;
    #pragma unroll 4
    for (int d = 0; d < DIM; d++) {
        float w = Wvo[d * DIM + h];
        #pragma unroll
        for (int j = 0; j < GPB; j++) acc[j] += xs[j][d] * w;
    }
    #pragma unroll
    for (int j = 0; j < GPB; j++)
        g_fvb[(o * NGRAPH + b0 + j) * DIM + h] = acc[j];
}

// ---------------- fused main kernel (512 threads, 16 warps) ----------------
#define MROWS 192
#define LDA 132   // A smem stride (conflict-free frag loads)
#define LDB 136   // B smem stride
#define OFF_A  0
#define OFF_WU (OFF_A + MROWS * LDA)        // 25344
#define OFF_FV (OFF_WU + 128 * LDB)         // 42752
#define OFF_WE (OFF_FV + 256)               // 43008
#define OFF_ER (OFF_WE + 128)               // 43136 (4 banks x 192)
#define OFF_AL (OFF_ER + 768)               // 43904
#define SMEM_FLOATS (OFF_AL + 192)          // 44096 -> 176384 B

__device__ __forceinline__ uint32_t to_tf32(float x) {
    uint32_t u;
    asm("cvt.rna.tf32.f32 %0, %1;" : "=r"(u) : "f"(x));
    return u;
}
__device__ __forceinline__ void mma_tf32(float c[4], const uint32_t a[4], const uint32_t b[2]) {
    asm volatile(
        "mma.sync.aligned.m16n8k8.row.col.f32.tf32.tf32.f32 "
        "{%0,%1,%2,%3}, {%4,%5,%6,%7}, {%8,%9}, {%0,%1,%2,%3};"
        : "+f"(c[0]), "+f"(c[1]), "+f"(c[2]), "+f"(c[3])
        : "r"(a[0]), "r"(a[1]), "r"(a[2]), "r"(a[3]), "r"(b[0]), "r"(b[1]));
}

__global__ void __launch_bounds__(512, 1) fused_kernel(const float* __restrict__ feats,
                                                       const float* __restrict__ Wu,
                                                       const float* __restrict__ We,
                                                       float* __restrict__ out) {
    extern __shared__ float sm[];
    float* sA  = sm + OFF_A;     // tf32-rounded feats, 192 rows
    float* sWu = sm + OFF_WU;    // tf32-rounded Wu[o]
    float* sFV = sm + OFF_FV;
    float* sWe = sm + OFF_WE;
    float* sER = sm + OFF_ER;
    float* sAL = sm + OFF_AL;

    const int tid   = threadIdx.x;
    const int g0    = blockIdx.x * 2;       // 2 graphs per CTA
    const int lane  = tid & 31;
    const int wid   = tid >> 5;
    const int warpM = wid >> 2;             // 0..3 -> 48 rows each
    const int warpN = wid & 3;              // 0..3 -> 32 cols each
    const int gid   = lane >> 2;
    const int tig   = lane & 3;

    // stage feats (pre-rounded to tf32): 182 rows + 10 zero pad rows
    {
        const float4* f4 = (const float4*)(feats + g0 * NPG * DIM);
        for (int i = tid; i < 182 * 32; i += 512) {
            int r = i >> 5, c = i & 31;
            float4 v = f4[i];
            uint32_t* d = (uint32_t*)(sA + r * LDA + c * 4);
            d[0] = to_tf32(v.x); d[1] = to_tf32(v.y);
            d[2] = to_tf32(v.z); d[3] = to_tf32(v.w);
        }
        if (tid < 10 * 32) {
            int r = 182 + (tid >> 5), c = tid & 31;
            *(float4*)(sA + r * LDA + c * 4) = make_float4(0.f, 0.f, 0.f, 0.f);
        }
    }

    for (int o = 0; o < ORDER; o++) {
        if (o > 0) __syncthreads();
        // stage Wu[o] (tf32), fv+bu for both graphs, We[o]
        {
            const float4* w4 = (const float4*)(Wu + o * DIM * DIM);
            for (int i = tid; i < 128 * 32; i += 512) {
                int r = i >> 5, c = i & 31;
                float4 v = w4[i];
                uint32_t* d = (uint32_t*)(sWu + r * LDB + c * 4);
                d[0] = to_tf32(v.x); d[1] = to_tf32(v.y);
                d[2] = to_tf32(v.z); d[3] = to_tf32(v.w);
            }
            if (tid < 256) {
                int g = tid >> 7, h = tid & 127;
                sFV[tid] = g_fvb[(o * NGRAPH + g0 + g) * DIM + h];
            }
            if (tid >= 256 && tid < 384) sWe[tid - 256] = We[o * DIM + (tid - 256)];
        }
        __syncthreads();

        float acc[3][4][4];
        #pragma unroll
        for (int mt = 0; mt < 3; mt++)
            #pragma unroll
            for (int nt = 0; nt < 4; nt++) {
                acc[mt][nt][0] = 0.f; acc[mt][nt][1] = 0.f;
                acc[mt][nt][2] = 0.f; acc[mt][nt][3] = 0.f;
            }

        #pragma unroll
        for (int ks = 0; ks < 16; ks++) {
            const int k0 = ks * 8;
            uint32_t afr[3][4];
            #pragma unroll
            for (int mt = 0; mt < 3; mt++) {
                const uint32_t* base =
                    (const uint32_t*)(sA + (warpM * 48 + mt * 16 + gid) * LDA + k0 + tig);
                afr[mt][0] = base[0];
                afr[mt][1] = base[8 * LDA];
                afr[mt][2] = base[4];
                afr[mt][3] = base[8 * LDA + 4];
            }
            uint32_t bfr[4][2];
            #pragma unroll
            for (int nt = 0; nt < 4; nt++) {
                const uint32_t* base =
                    (const uint32_t*)(sWu + (k0 + tig) * LDB + warpN * 32 + nt * 8 + gid);
                bfr[nt][0] = base[0];
                bfr[nt][1] = base[4 * LDB];
            }
            #pragma unroll
            for (int mt = 0; mt < 3; mt++)
                #pragma unroll
                for (int nt = 0; nt < 4; nt++)
                    mma_tf32(acc[mt][nt], afr[mt], bfr[nt]);
        }

        // epilogue: e-row partials = sum_h sigmoid(acc + fv) * We[h]
        float ep[3][2];
        #pragma unroll
        for (int mt = 0; mt < 3; mt++) { ep[mt][0] = 0.f; ep[mt][1] = 0.f; }
        #pragma unroll
        for (int mt = 0; mt < 3; mt++) {
            int m0 = warpM * 48 + mt * 16 + gid;
            int m1 = m0 + 8;
            int fo0 = (m0 < NPG ? 0 : DIM);
            int fo1 = (m1 < NPG ? 0 : DIM);
            #pragma unroll
            for (int nt = 0; nt < 4; nt++) {
                int h = warpN * 32 + nt * 8 + tig * 2;
                float we0 = sWe[h], we1 = sWe[h + 1];
                if (m0 < 182) {
                    float v0 = acc[mt][nt][0] + sFV[fo0 + h];
                    float v1 = acc[mt][nt][1] + sFV[fo0 + h + 1];
                    ep[mt][0] += __fdividef(we0, 1.f + __expf(-v0))
                               + __fdividef(we1, 1.f + __expf(-v1));
                }
                if (m1 < 182) {
                    float v2 = acc[mt][nt][2] + sFV[fo1 + h];
                    float v3 = acc[mt][nt][3] + sFV[fo1 + h + 1];
                    ep[mt][1] += __fdividef(we0, 1.f + __expf(-v2))
                               + __fdividef(we1, 1.f + __expf(-v3));
                }
            }
        }
        #pragma unroll
        for (int mt = 0; mt < 3; mt++)
            #pragma unroll
            for (int q = 0; q < 2; q++) {
                float v = ep[mt][q];
                v += __shfl_xor_sync(0xffffffffu, v, 1);
                v += __shfl_xor_sync(0xffffffffu, v, 2);
                if (tig == 0)
                    sER[warpN * 192 + warpM * 48 + mt * 16 + gid + q * 8] = v;
            }
        __syncthreads();

        // per-graph softmax over 91 nodes (warp 0 -> graph 0, warp 1 -> graph 1)
        if (wid < 2) {
            int gbase = wid * NPG;
            float ev[3];
            #pragma unroll
            for (int j = 0; j < 3; j++) {
                int r = lane + 32 * j;
                ev[j] = (r < NPG) ? (sER[gbase + r] + sER[192 + gbase + r] +
                                     sER[384 + gbase + r] + sER[576 + gbase + r])
                                  : -1e30f;
            }
            float mx = fmaxf(ev[0], fmaxf(ev[1], ev[2]));
            #pragma unroll
            for (int s = 16; s; s >>= 1)
                mx = fmaxf(mx, __shfl_xor_sync(0xffffffffu, mx, s));
            float sum = 0.f;
            #pragma unroll
            for (int j = 0; j < 3; j++) {
                ev[j] = (lane + 32 * j < NPG) ? __expf(ev[j] - mx) : 0.f;
                sum += ev[j];
            }
            #pragma unroll
            for (int s = 16; s; s >>= 1)
                sum += __shfl_xor_sync(0xffffffffu, sum, s);
            float inv = 1.f / sum;
            #pragma unroll
            for (int j = 0; j < 3; j++) {
                int r = lane + 32 * j;
                if (r < NPG) sAL[gbase + r] = ev[j] * inv;
            }
        }
        __syncthreads();

        // rst[b,o,:] = sum_m alpha[m] * feats[m,:]  (split rows across 2 halves)
        {
            int g    = tid >> 8;          // 0..1 graph
            int part = (tid >> 7) & 1;    // 0..1 row half
            int h    = tid & 127;
            int r0i  = part * 46;
            int cnt  = part ? 45 : 46;
            const float* aBase  = sA + (g * NPG + r0i) * LDA + h;
            const float* alBase = sAL + g * NPG + r0i;
            float r0 = 0.f;
            #pragma unroll 5
            for (int r = 0; r < cnt; r++) r0 += alBase[r] * aBase[r * LDA];
            if (part) sER[g * 128 + h] = r0;   // reuse sER as partial buffer
            __syncthreads();
            if (!part)
                out[((g0 + g) * ORDER + o) * DIM + h] = r0 + sER[g * 128 + h];
        }
    }
}

extern "C" void kernel_launch(void* const* d_in, const int* in_sizes, int n_in,
                              void* d_out, int out_size) {
    const float* feats    = (const float*)d_in[0];
    const float* Wu       = (const float*)d_in[1];
    const float* bu       = (const float*)d_in[2];
    const float* Wv       = (const float*)d_in[3];
    const float* We       = (const float*)d_in[4];
    const int*   last_idx = (const int*)d_in[6];
    float* out = (float*)d_out;

    fvb_kernel<<<ORDER * (NGRAPH / 16), 128>>>(feats, Wv, bu, last_idx);

    cudaFuncSetAttribute(fused_kernel, cudaFuncAttributeMaxDynamicSharedMemorySize,
                         SMEM_FLOATS * (int)sizeof(float));
    fused_kernel<<<NGRAPH / 2, 512, SMEM_FLOATS * sizeof(float)>>>(feats, Wu, We, out);
}